// round 17
// baseline (speedup 1.0000x reference)
#include <cuda_runtime.h>
#include <math.h>
#include <stdint.h>

#define E_DIM   1024
#define S_LEN   2048
#define N_BATCH 2
#define N_HEADS 16
#define H_DIM   64
#define M_ROWS  (N_BATCH * S_LEN)   // 4096
#define ME      ((size_t)M_ROWS * E_DIM)   // 4M elems
#define EE      ((size_t)E_DIM * E_DIM)    // 1M elems

// ---------- global scratch (allocation-free) ----------
__device__ uint32_t s_xq_hi[ME];
__device__ uint32_t s_xk_hi[ME];
__device__ uint32_t s_xv_hi[ME];
__device__ uint32_t s_wq_hi[EE];
__device__ uint32_t s_wk_hi[EE];
__device__ uint32_t s_wv_hi[EE];
__device__ uint32_t s_wo_hi[EE];
__device__ uint32_t s_q_hi[ME];
__device__ uint32_t s_k_hi[ME];
__device__ uint32_t s_vt_hi[ME];   // [bh][d][s]
__device__ uint32_t s_o_hi[ME];

// ===================== helpers =====================
__device__ __forceinline__ uint32_t smem_u32(const void* p) {
    uint32_t a;
    asm("{ .reg .u64 t; cvta.to.shared.u64 t, %1; cvt.u32.u64 %0, t; }" : "=r"(a) : "l"(p));
    return a;
}
__device__ __forceinline__ uint32_t cvt_tf32(float f) {
    uint32_t u;
    asm("cvt.rna.tf32.f32 %0, %1;" : "=r"(u) : "f"(f));
    return u;
}
__device__ __forceinline__ uint4 hi4(float4 v) {
    uint4 h;
    h.x = cvt_tf32(v.x); h.y = cvt_tf32(v.y);
    h.z = cvt_tf32(v.z); h.w = cvt_tf32(v.w);
    return h;
}

#define CP16(dst, src) \
    asm volatile("cp.async.cg.shared.global [%0], [%1], 16;" :: "r"(dst), "l"(src))
#define CPCOMMIT() asm volatile("cp.async.commit_group;" ::: "memory")
#define CPWAIT1()  asm volatile("cp.async.wait_group 1;" ::: "memory")
#define CPWAIT0()  asm volatile("cp.async.wait_group 0;" ::: "memory")

#define LDSM_X4(r0, r1, r2, r3, addr)                                          \
    asm volatile("ldmatrix.sync.aligned.m8n8.x4.shared.b16 {%0,%1,%2,%3}, [%4];" \
                 : "=r"(r0), "=r"(r1), "=r"(r2), "=r"(r3) : "r"(addr))
#define LDSM_X2(r0, r1, addr)                                                  \
    asm volatile("ldmatrix.sync.aligned.m8n8.x2.shared.b16 {%0,%1}, [%2];"     \
                 : "=r"(r0), "=r"(r1) : "r"(addr))

#define MMA_TF32(d, A, b0v, b1v)                                               \
    asm volatile("mma.sync.aligned.m16n8k8.row.col.f32.tf32.tf32.f32 "         \
                 "{%0,%1,%2,%3}, {%4,%5,%6,%7}, {%8,%9}, {%0,%1,%2,%3};"       \
                 : "+f"((d)[0]), "+f"((d)[1]), "+f"((d)[2]), "+f"((d)[3])      \
                 : "r"((A)[0]), "r"((A)[1]), "r"((A)[2]), "r"((A)[3]),         \
                   "r"(b0v), "r"(b1v))

#define STS64(addr, v0, v1) \
    asm volatile("st.shared.v2.f32 [%0], {%1,%2};" :: "r"(addr), "f"(v0), "f"(v1))

// ===================== fused pre-split kernels (hi only) =====================
__global__ __launch_bounds__(256) void split_me_kernel(
    const float4* __restrict__ q, const float4* __restrict__ k, const float4* __restrict__ v)
{
    const int t = blockIdx.y;
    const float4* src = (t == 0) ? q : ((t == 1) ? k : v);
    uint4* hi = (t == 0) ? (uint4*)s_xq_hi : ((t == 1) ? (uint4*)s_xk_hi : (uint4*)s_xv_hi);
    int i = blockIdx.x * 256 + threadIdx.x;
    hi[i] = hi4(src[i]);
}
__global__ __launch_bounds__(256) void split_w_kernel(
    const float4* __restrict__ wq, const float4* __restrict__ wk,
    const float4* __restrict__ wv, const float4* __restrict__ wo)
{
    const int t = blockIdx.y;
    const float4* src = (t == 0) ? wq : ((t == 1) ? wk : ((t == 2) ? wv : wo));
    uint4* hi = (t == 0) ? (uint4*)s_wq_hi : ((t == 1) ? (uint4*)s_wk_hi
              : ((t == 2) ? (uint4*)s_wv_hi : (uint4*)s_wo_hi));
    int i = blockIdx.x * 256 + threadIdx.x;
    hi[i] = hi4(src[i]);
}

// ===================== GEMM: pure tf32, K-chunk 32 =====================
// Chunk stored as two 16-float sub-tiles (A0|A1|B0|B1, each 10240B, 80B rows).
// Halves barrier count vs K-chunk 16.
#define NCHUNK32 (E_DIM / 32)   // 32
#define ROWB     80
#define SUB_B    10240u
#define STAGE_B  40960u
#define GEMM_SMEM (2 * 40960)

__global__ __launch_bounds__(256, 2) void gemm_tc_kernel(
    const float* __restrict__ bq, const float* __restrict__ bk,
    const float* __restrict__ bv, const float* __restrict__ bo,
    float* __restrict__ out, int is_out)
{
    extern __shared__ char smem[];
    const int z = blockIdx.z;
    const uint32_t *Xhi, *Whi;
    const float* Bv;
    int mode;
    if (is_out) { Xhi = s_o_hi;  Whi = s_wo_hi; Bv = bo; mode = 3; }
    else if (z == 0) { Xhi = s_xq_hi; Whi = s_wq_hi; Bv = bq; mode = 0; }
    else if (z == 1) { Xhi = s_xk_hi; Whi = s_wk_hi; Bv = bk; mode = 1; }
    else             { Xhi = s_xv_hi; Whi = s_wv_hi; Bv = bv; mode = 2; }

    const int tid  = threadIdx.x;
    const int lane = tid & 31;
    const int wid  = tid >> 5;
    const int wm   = wid >> 2;
    const int wn   = wid & 3;
    const int m0 = blockIdx.y * 128;
    const int n0 = blockIdx.x * 128;

    const uint32_t sb = smem_u32(smem);

    const int prow = tid >> 2;
    const int pc4  = tid & 3;
    const size_t xoff = (size_t)(m0 + prow) * E_DIM + pc4 * 4;
    const size_t woff = (size_t)(n0 + prow) * E_DIM + pc4 * 4;
    const uint32_t pd = (uint32_t)prow * ROWB + (uint32_t)pc4 * 16;

    #define GCP_CHUNK(c, st) do {                                              \
        uint32_t base_ = sb + (uint32_t)(st) * STAGE_B + pd;                   \
        size_t ko_ = (size_t)(c) * 32;                                         \
        _Pragma("unroll")                                                      \
        for (int r = 0; r < 2; ++r) {                                          \
            size_t sx_ = xoff + (size_t)r * 64 * E_DIM + ko_;                  \
            size_t sw_ = woff + (size_t)r * 64 * E_DIM + ko_;                  \
            uint32_t dd_ = base_ + (uint32_t)r * 5120;                         \
            _Pragma("unroll")                                                  \
            for (int p = 0; p < 2; ++p) {                                      \
                CP16(dd_ + (uint32_t)p * SUB_B,               Xhi + sx_ + p * 16); \
                CP16(dd_ + 2u * SUB_B + (uint32_t)p * SUB_B,  Whi + sw_ + p * 16); \
            }                                                                  \
        }                                                                      \
    } while (0)

    GCP_CHUNK(0, 0); CPCOMMIT();
    GCP_CHUNK(1, 1); CPCOMMIT();

    const int i4 = lane >> 3, r8 = lane & 7;
    const uint32_t a_off = (uint32_t)(wm * 64 + ((i4 & 1) << 3) + r8) * ROWB
                         + (uint32_t)((i4 >> 1) << 4);
    const uint32_t b_off = (uint32_t)(wn * 32 + r8) * ROWB
                         + (uint32_t)((i4 & 1) << 4);

    float acc[4][4][4];
#pragma unroll
    for (int mt = 0; mt < 4; ++mt)
#pragma unroll
        for (int nt = 0; nt < 4; ++nt)
#pragma unroll
            for (int r = 0; r < 4; ++r) acc[mt][nt][r] = 0.f;

    for (int c = 0; c < NCHUNK32; ++c) {
        CPWAIT1();
        __syncthreads();
        const uint32_t stb = sb + (uint32_t)(c & 1) * STAGE_B;

#pragma unroll
        for (int part = 0; part < 2; ++part) {
            const uint32_t ab = stb + (uint32_t)part * SUB_B + a_off;
            const uint32_t bb = stb + 2u * SUB_B + (uint32_t)part * SUB_B + b_off;
#pragma unroll
            for (int ks = 0; ks < 2; ++ks) {
                uint32_t bhv[4][2];
#pragma unroll
                for (int nt = 0; nt < 4; ++nt)
                    LDSM_X2(bhv[nt][0], bhv[nt][1], bb + nt * (8 * ROWB) + ks * 32);
#pragma unroll
                for (int mt = 0; mt < 4; ++mt) {
                    uint32_t ah[4];
                    LDSM_X4(ah[0], ah[1], ah[2], ah[3], ab + mt * (16 * ROWB) + ks * 32);
#pragma unroll
                    for (int nt = 0; nt < 4; ++nt)
                        MMA_TF32(acc[mt][nt], ah, bhv[nt][0], bhv[nt][1]);
                }
            }
        }

        __syncthreads();
        if (c + 2 < NCHUNK32) GCP_CHUNK(c + 2, c & 1);
        CPCOMMIT();
    }

    if (mode == 3) {
#pragma unroll
        for (int nt = 0; nt < 4; ++nt) {
            const int col = n0 + wn * 32 + nt * 8 + 2 * (lane & 3);
            const float bx = __ldg(&Bv[col]);
            const float by = __ldg(&Bv[col + 1]);
#pragma unroll
            for (int mt = 0; mt < 4; ++mt) {
                const int r0i = m0 + wm * 64 + mt * 16 + (lane >> 2);
                *(float2*)&out[(size_t)r0i * E_DIM + col] =
                    make_float2(acc[mt][nt][0] + bx, acc[mt][nt][1] + by);
                *(float2*)&out[(size_t)(r0i + 8) * E_DIM + col] =
                    make_float2(acc[mt][nt][2] + bx, acc[mt][nt][3] + by);
            }
        }
    } else if (mode == 2) {
        const int bq2 = m0 >> 11;
#pragma unroll
        for (int nt = 0; nt < 4; ++nt) {
            const int col = n0 + wn * 32 + nt * 8 + 2 * (lane & 3);
            const int hh = col >> 6, dd = col & 63;
            const float bx = __ldg(&Bv[col]);
            const float by = __ldg(&Bv[col + 1]);
            const size_t b0i = ((size_t)(bq2 * 16 + hh) * 64 + dd) * S_LEN;
            const size_t b1i = b0i + S_LEN;
#pragma unroll
            for (int mt = 0; mt < 4; ++mt) {
                const int s = (m0 & 2047) + wm * 64 + mt * 16 + (lane >> 2);
                s_vt_hi[b0i + s]     = cvt_tf32(acc[mt][nt][0] + bx);
                s_vt_hi[b1i + s]     = cvt_tf32(acc[mt][nt][1] + by);
                s_vt_hi[b0i + s + 8] = cvt_tf32(acc[mt][nt][2] + bx);
                s_vt_hi[b1i + s + 8] = cvt_tf32(acc[mt][nt][3] + by);
            }
        }
    } else {
        uint32_t* Yh = (mode == 0) ? s_q_hi : s_k_hi;
#pragma unroll
        for (int nt = 0; nt < 4; ++nt) {
            const int col = n0 + wn * 32 + nt * 8 + 2 * (lane & 3);
            const float bx = __ldg(&Bv[col]);
            const float by = __ldg(&Bv[col + 1]);
#pragma unroll
            for (int mt = 0; mt < 4; ++mt) {
                const int r0i = m0 + wm * 64 + mt * 16 + (lane >> 2);
                *(uint2*)&Yh[(size_t)r0i * E_DIM + col] =
                    make_uint2(cvt_tf32(acc[mt][nt][0] + bx), cvt_tf32(acc[mt][nt][1] + by));
                *(uint2*)&Yh[(size_t)(r0i + 8) * E_DIM + col] =
                    make_uint2(cvt_tf32(acc[mt][nt][2] + bx), cvt_tf32(acc[mt][nt][3] + by));
            }
        }
    }
}

// ===================== Causal flash attention: full-row warps, no named barriers =====================
// 8 warps x 16 full rows (all 64 cols). Softmax entirely intra-warp. P warp-private.
// K/VT single-stage (co-resident CTA hides latency), 2 CTAs/SM.
// smem: Qhi 32K | K 16K | VT 16K | P (8 warps x 4K) 32K = 98304; x2 = 196K.
#define AQH   0u
#define AKB   32768u
#define AVB   49152u
#define APH   65536u      // + w*4096
#define ATTN_SMEM 98304

__global__ __launch_bounds__(256, 2) void attn_tc_kernel(void)
{
    extern __shared__ char smem[];
    const uint32_t sb = smem_u32(smem);

    const int tid = threadIdx.x, lane = tid & 31, w = tid >> 5;
    const int i = (int)gridDim.x - 1 - (int)blockIdx.x;   // heavy tiles first
    const int bh = blockIdx.y;
    const int b = bh >> 4, h = bh & 15;

    const size_t qbase  = ((size_t)b * S_LEN + i * 128) * E_DIM + h * 64;
    const size_t kbase  = (size_t)b * S_LEN * E_DIM + h * 64;
    const size_t vtbase = (size_t)bh * 64 * S_LEN;

    // Q: 128 rows x 16 slots, hi only
#pragma unroll
    for (int l = 0; l < 8; ++l) {
        int idx = tid + l * 256, row = idx >> 4, sl = idx & 15;
        uint32_t sw = (uint32_t)(row * 256 + ((sl ^ (row & 7)) << 4));
        CP16(sb + AQH + sw, s_q_hi + qbase + (size_t)row * E_DIM + sl * 4);
    }

    #define ISSUE_K(j_) do {                                                   \
        _Pragma("unroll")                                                      \
        for (int l = 0; l < 4; ++l) {                                          \
            int idx_ = tid + l * 256, row_ = idx_ >> 4, sl_ = idx_ & 15;       \
            uint32_t sw_ = (uint32_t)(row_ * 256 + ((sl_ ^ (row_ & 7)) << 4)); \
            CP16(sb + AKB + sw_, s_k_hi + kbase + (size_t)((j_) * 64 + row_) * E_DIM + sl_ * 4); \
        }                                                                      \
    } while (0)

    #define ISSUE_VT(j_) do {                                                  \
        _Pragma("unroll")                                                      \
        for (int l = 0; l < 4; ++l) {                                          \
            int idx_ = tid + l * 256, row_ = idx_ >> 4, sl_ = idx_ & 15;       \
            uint32_t sw_ = (uint32_t)(row_ * 256 + ((sl_ ^ (row_ & 7)) << 4)); \
            CP16(sb + AVB + sw_, s_vt_hi + vtbase + (size_t)row_ * S_LEN + (j_) * 64 + sl_ * 4); \
        }                                                                      \
    } while (0)

    const int jmax = 2 * i + 1;

    ISSUE_K(0);
    ISSUE_VT(0);
    CPCOMMIT();                 // G0: Q + K0 + VT0

    const int i4 = lane >> 3, r8 = lane & 7;
    const int lr = lane >> 2;
    const int lc0 = 2 * (lane & 3);
    const int arow = ((i4 & 1) << 3) + r8;     // A-frag row within 16
    const int aslot_hi = i4 >> 1;
    const int pslot_lo = (lane & 3) >> 1;
    const uint32_t pword = (uint32_t)((lane & 1) << 3);
    const uint32_t pg = sb + APH + (uint32_t)w * 4096;   // warp-private P (16 rows)
    const int brow_off = ((i4 >> 1) << 3) + r8;          // B x4: rows +0/+8, slot bit
    const int bslot_lo = i4 & 1;
    const int qr0 = i * 128 + w * 16 + lr;               // global q row of regs 0,1

    float m_prev[2] = {-INFINITY, -INFINITY};
    float lsum[2] = {0.f, 0.f};
    float o[8][4];
#pragma unroll
    for (int nt = 0; nt < 8; ++nt)
#pragma unroll
        for (int r = 0; r < 4; ++r) o[nt][r] = 0.f;

    for (int j = 0; j <= jmax; ++j) {
        CPWAIT0();              // K(j), VT(j) resident (j=0 also covers Q)
        __syncthreads();

        // ---- S = Qhi * Khi (warp owns 16 rows x 64 cols) ----
        float sacc[8][4];
#pragma unroll
        for (int nt = 0; nt < 8; ++nt)
#pragma unroll
            for (int r = 0; r < 4; ++r) sacc[nt][r] = 0.f;

#pragma unroll
        for (int ks = 0; ks < 8; ++ks) {
            uint32_t khv[8][2];
#pragma unroll
            for (int nt2 = 0; nt2 < 4; ++nt2) {
                const int brow = nt2 * 16 + brow_off;
                const uint32_t boff = (uint32_t)(brow * 256
                    + ((((ks << 1) | bslot_lo) ^ (brow & 7)) << 4));
                LDSM_X4(khv[nt2 * 2][0], khv[nt2 * 2][1],
                        khv[nt2 * 2 + 1][0], khv[nt2 * 2 + 1][1], sb + AKB + boff);
            }
            const int qrow = w * 16 + arow;
            const uint32_t aoff = (uint32_t)(qrow * 256
                + ((((ks << 1) | aslot_hi) ^ (qrow & 7)) << 4));
            uint32_t ah[4];
            LDSM_X4(ah[0], ah[1], ah[2], ah[3], sb + AQH + aoff);
#pragma unroll
            for (int nt = 0; nt < 8; ++nt)
                MMA_TF32(sacc[nt], ah, khv[nt][0], khv[nt][1]);
        }

        // ---- mask + softmax (fully intra-warp) ----
        float mloc0 = -INFINITY, mloc1 = -INFINITY;
#pragma unroll
        for (int nt = 0; nt < 8; ++nt) {
            const int c0 = j * 64 + (nt << 3) + lc0;
            float s0 = sacc[nt][0] * 0.125f, s1 = sacc[nt][1] * 0.125f;
            float s2 = sacc[nt][2] * 0.125f, s3 = sacc[nt][3] * 0.125f;
            if (c0     > qr0)     s0 = -INFINITY;
            if (c0 + 1 > qr0)     s1 = -INFINITY;
            if (c0     > qr0 + 8) s2 = -INFINITY;
            if (c0 + 1 > qr0 + 8) s3 = -INFINITY;
            sacc[nt][0] = s0; sacc[nt][1] = s1;
            sacc[nt][2] = s2; sacc[nt][3] = s3;
            mloc0 = fmaxf(mloc0, fmaxf(s0, s1));
            mloc1 = fmaxf(mloc1, fmaxf(s2, s3));
        }
        mloc0 = fmaxf(mloc0, __shfl_xor_sync(0xffffffffu, mloc0, 1));
        mloc0 = fmaxf(mloc0, __shfl_xor_sync(0xffffffffu, mloc0, 2));
        mloc1 = fmaxf(mloc1, __shfl_xor_sync(0xffffffffu, mloc1, 1));
        mloc1 = fmaxf(mloc1, __shfl_xor_sync(0xffffffffu, mloc1, 2));

        const float m_new0 = fmaxf(m_prev[0], mloc0);
        const float m_new1 = fmaxf(m_prev[1], mloc1);
        const float fac0 = (m_prev[0] == -INFINITY) ? 0.f : __expf(m_prev[0] - m_new0);
        const float fac1 = (m_prev[1] == -INFINITY) ? 0.f : __expf(m_prev[1] - m_new1);
        m_prev[0] = m_new0; m_prev[1] = m_new1;

        // P rounded to tf32; denominator accumulated from the ROUNDED values.
        float ls0 = 0.f, ls1 = 0.f;
        const int rA = lr, rB = lr + 8;
        const uint32_t rowA_h = pg + rA * 256, rowB_h = pg + rB * 256;
#pragma unroll
        for (int nt = 0; nt < 8; ++nt) {
            const uint32_t h0 = cvt_tf32(__expf(sacc[nt][0] - m_new0));
            const uint32_t h1 = cvt_tf32(__expf(sacc[nt][1] - m_new0));
            const uint32_t h2v = cvt_tf32(__expf(sacc[nt][2] - m_new1));
            const uint32_t h3 = cvt_tf32(__expf(sacc[nt][3] - m_new1));
            ls0 += __uint_as_float(h0) + __uint_as_float(h1);
            ls1 += __uint_as_float(h2v) + __uint_as_float(h3);
            const uint32_t slot = (uint32_t)((nt << 1) | pslot_lo);
            STS64(rowA_h + ((slot ^ (rA & 7)) << 4) + pword,
                  __uint_as_float(h0), __uint_as_float(h1));
            STS64(rowB_h + ((slot ^ (rB & 7)) << 4) + pword,
                  __uint_as_float(h2v), __uint_as_float(h3));
        }
        ls0 += __shfl_xor_sync(0xffffffffu, ls0, 1);
        ls0 += __shfl_xor_sync(0xffffffffu, ls0, 2);
        ls1 += __shfl_xor_sync(0xffffffffu, ls1, 1);
        ls1 += __shfl_xor_sync(0xffffffffu, ls1, 2);
        lsum[0] = lsum[0] * fac0 + ls0;
        lsum[1] = lsum[1] * fac1 + ls1;

#pragma unroll
        for (int nt = 0; nt < 8; ++nt) {
            o[nt][0] *= fac0; o[nt][1] *= fac0;
            o[nt][2] *= fac1; o[nt][3] *= fac1;
        }
        __syncwarp();   // P stores visible to this warp's ldmatrix

        // ---- O += Phat * Vhi ----
#pragma unroll
        for (int ks = 0; ks < 8; ++ks) {
            uint32_t vhv[8][2];
#pragma unroll
            for (int nt2 = 0; nt2 < 4; ++nt2) {
                const int vrow = nt2 * 16 + brow_off;
                const uint32_t voff = (uint32_t)(vrow * 256
                    + ((((ks << 1) | bslot_lo) ^ (vrow & 7)) << 4));
                LDSM_X4(vhv[nt2 * 2][0], vhv[nt2 * 2][1],
                        vhv[nt2 * 2 + 1][0], vhv[nt2 * 2 + 1][1], sb + AVB + voff);
            }
            const uint32_t poff = (uint32_t)(arow * 256
                + ((((ks << 1) | aslot_hi) ^ (arow & 7)) << 4));
            uint32_t ph[4];
            LDSM_X4(ph[0], ph[1], ph[2], ph[3], pg + poff);
#pragma unroll
            for (int nt = 0; nt < 8; ++nt)
                MMA_TF32(o[nt], ph, vhv[nt][0], vhv[nt][1]);
        }

        __syncthreads();   // all reads of K/VT done before single-buffer refill
        if (j < jmax) {
            ISSUE_K(j + 1);
            ISSUE_VT(j + 1);
            CPCOMMIT();
        }
    }

    // ---- epilogue: O hi only ----
    const float inv0 = 1.f / lsum[0];
    const float inv1 = 1.f / lsum[1];
    const size_t rowA = ((size_t)b * S_LEN + i * 128 + w * 16 + lr) * E_DIM;
    const size_t rowB = rowA + (size_t)8 * E_DIM;
#pragma unroll
    for (int nt = 0; nt < 8; ++nt) {
        const int col = h * 64 + (nt << 3) + lc0;
        *(uint2*)&s_o_hi[rowA + col] =
            make_uint2(cvt_tf32(o[nt][0] * inv0), cvt_tf32(o[nt][1] * inv0));
        *(uint2*)&s_o_hi[rowB + col] =
            make_uint2(cvt_tf32(o[nt][2] * inv1), cvt_tf32(o[nt][3] * inv1));
    }
}

// ===================== launch =====================
extern "C" void kernel_launch(void* const* d_in, const int* in_sizes, int n_in,
                              void* d_out, int out_size)
{
    (void)in_sizes; (void)n_in; (void)out_size;
    const float* q  = (const float*)d_in[0];
    const float* k  = (const float*)d_in[1];
    const float* v  = (const float*)d_in[2];
    const float* Wq = (const float*)d_in[3];
    const float* bq = (const float*)d_in[4];
    const float* Wk = (const float*)d_in[5];
    const float* bk = (const float*)d_in[6];
    const float* Wv = (const float*)d_in[7];
    const float* bv = (const float*)d_in[8];
    const float* Wo = (const float*)d_in[9];
    const float* bo = (const float*)d_in[10];
    float* out = (float*)d_out;

    cudaFuncSetAttribute(gemm_tc_kernel, cudaFuncAttributeMaxDynamicSharedMemorySize, GEMM_SMEM);
    cudaFuncSetAttribute(attn_tc_kernel, cudaFuncAttributeMaxDynamicSharedMemorySize, ATTN_SMEM);

    // fused pre-split (2 launches; everything hi-only)
    dim3 gridSM((unsigned)(ME / 4 / 256), 3);
    split_me_kernel<<<gridSM, 256>>>((const float4*)q, (const float4*)k, (const float4*)v);
    dim3 gridSW((unsigned)(EE / 4 / 256), 4);
    split_w_kernel<<<gridSW, 256>>>((const float4*)Wq, (const float4*)Wk,
                                    (const float4*)Wv, (const float4*)Wo);

    // Q/K/V projections
    dim3 gridP(E_DIM / 128, M_ROWS / 128, 3);
    gemm_tc_kernel<<<gridP, 256, GEMM_SMEM>>>(bq, bk, bv, bo, out, 0);

    // causal flash attention
    dim3 gridA(S_LEN / 128, N_BATCH * N_HEADS);
    attn_tc_kernel<<<gridA, 256, ATTN_SMEM>>>();

    // output projection
    dim3 gridO(E_DIM / 128, M_ROWS / 128, 1);
    gemm_tc_kernel<<<gridO, 256, GEMM_SMEM>>>(bq, bk, bv, bo, out, 1);
}